// round 7
// baseline (speedup 1.0000x reference)
#include <cuda_runtime.h>
#include <math.h>
#include <stdint.h>

constexpr int Bb = 32;
constexpr int Hh = 56;
constexpr int Ww = 56;
constexpr int Cc = 128;
constexpr int Nn = Hh * Ww;              // 3136
constexpr int Mm = Bb * Nn;              // 100352
constexpr size_t MC = (size_t)Mm * Cc;

__device__ float g_t0[MC];
__device__ float g_t1[MC];
__device__ float g_x1a[MC];
__device__ float g_x2a[MC];
__device__ float g_q[MC];
__device__ float g_k[MC];
__device__ float g_v[MC];
__device__ float g_att[MC];
__device__ float g_stats[2 * Mm];        // LN mean | rstd
__device__ float g_part[784 * 256];
__device__ float g_scale[Cc];
__device__ float g_shift[Cc];

__device__ __forceinline__ float tf32r(float x) {
    uint32_t u;
    asm("cvt.rna.tf32.f32 %0, %1;" : "=r"(u) : "f"(x));
    return __uint_as_float(u);
}

__device__ __forceinline__ void mma_tf32(float* c, const float4& a, const float2& b) {
    asm volatile(
        "mma.sync.aligned.m16n8k8.row.col.f32.tf32.tf32.f32 "
        "{%0,%1,%2,%3}, {%4,%5,%6,%7}, {%8,%9}, {%0,%1,%2,%3};"
        : "+f"(c[0]), "+f"(c[1]), "+f"(c[2]), "+f"(c[3])
        : "r"(__float_as_uint(a.x)), "r"(__float_as_uint(a.y)),
          "r"(__float_as_uint(a.z)), "r"(__float_as_uint(a.w)),
          "r"(__float_as_uint(b.x)), "r"(__float_as_uint(b.y)));
}

// ---------------------------------------------------------------------------
// Per-channel roll. MODE 0: H,+c  1: W,+c  2: W,-c
// ---------------------------------------------------------------------------
template <int MODE>
__launch_bounds__(256)
__global__ void roll_k(const float* __restrict__ in, float* __restrict__ out) {
    __shared__ float tile[56 * 128];
    const int tid = threadIdx.x;
    const int b = blockIdx.x / 56;
    const int f = blockIdx.x % 56;
    const size_t base   = (MODE == 0) ? ((size_t)b * Nn + f) * 128
                                      : ((size_t)(b * 56 + f) * 56) * 128;
    const int    stride = (MODE == 0) ? 56 * 128 : 128;

    #pragma unroll
    for (int e = tid; e < 56 * 32; e += 256) {
        int rowi = e >> 5, c4 = e & 31;
        ((float4*)tile)[rowi * 32 + c4] =
            *(const float4*)(in + base + (size_t)rowi * stride + c4 * 4);
    }
    __syncthreads();

    #pragma unroll
    for (int e = tid; e < 56 * 128; e += 256) {
        int pos = e >> 7, c = e & 127;
        int cm = c % 56;
        int src = (MODE == 2) ? pos + cm : pos - cm;
        if (src < 0) src += 56;
        if (src >= 56) src -= 56;
        out[base + (size_t)pos * stride + c] = tile[src * 128 + c];
    }
}

// ---------------------------------------------------------------------------
// TF32 GEMM: barrier-free mainloop. Each warp gathers its OWN A fragments
// directly from global to registers (duplicate reads hit L1). B resident in
// fragment-order smem (64 KB chunk of 128 k-cols; K=256 swaps chunk once).
// AMODE: 0 plain A[M,K]; 1 split [A0|A1]+per-col affine on A1 (BN fold);
//        2 split [A0|A1]+per-row LayerNorm fold. QKV: grid.y selects B/bias/C.
// ---------------------------------------------------------------------------
enum { EPI_GELU = 0, EPI_BIAS = 1, EPI_RES = 2 };
constexpr int SM_ALL = 16 * 16 * 32 * 8;   // 64 KB (one 128-k B chunk)

template <int K, int EPI, int AMODE, bool BT, bool QKV>
__launch_bounds__(256, 2)
__global__ void gemm_k(const float* __restrict__ A0, const float* __restrict__ A1,
                       const float* __restrict__ B0, const float* __restrict__ B1,
                       const float* __restrict__ B2,
                       const float* __restrict__ bias0, const float* __restrict__ bias1,
                       const float* __restrict__ bias2,
                       const float* __restrict__ res,
                       const float* __restrict__ p0, const float* __restrict__ p1,
                       const float* __restrict__ p2, const float* __restrict__ p3,
                       float* __restrict__ C0, float* __restrict__ C1,
                       float* __restrict__ C2) {
    extern __shared__ float smem[];
    float2* Bs = (float2*)smem;                 // [16 k8][16 nt][32 lane]

    const float* Bm = B0;
    const float* bias = bias0;
    float* Cm = C0;
    if (QKV) {
        int y = blockIdx.y;
        if (y == 1) { Bm = B1; bias = bias1; Cm = C1; }
        else if (y == 2) { Bm = B2; bias = bias2; Cm = C2; }
    }

    const int tid  = threadIdx.x;
    const int lane = tid & 31;
    const int wid  = tid >> 5;
    const int wm   = wid & 3;
    const int wn   = wid >> 2;
    const int row0 = blockIdx.x * 128;
    const int lr   = lane >> 2;
    const int lc   = lane & 3;

    auto loadB = [&](int ko) {
        for (int frag = wid; frag < 256; frag += 8) {
            int k8l = frag >> 4, nt = frag & 15;
            int kk = ko + k8l * 8 + lc, n = nt * 8 + lr;
            float b0v, b1v;
            if (BT) { b0v = Bm[(size_t)n * K + kk];   b1v = Bm[(size_t)n * K + kk + 4]; }
            else    { b0v = Bm[(size_t)kk * 128 + n]; b1v = Bm[(size_t)(kk + 4) * 128 + n]; }
            Bs[frag * 32 + lane] = make_float2(tf32r(b0v), tf32r(b1v));
        }
    };

    // per-warp A row bases and (optional) LN stats for its 4 fragment rows
    const int rbase = row0 + wm * 32 + lr;      // + {0,8,16,24}
    float mj[4] = {}, rj[4] = {};
    if (AMODE == 2) {
        #pragma unroll
        for (int j = 0; j < 4; j++) { mj[j] = p0[rbase + j * 8]; rj[j] = p1[rbase + j * 8]; }
    }

    auto fetch1 = [&](int r, int si, int c) -> float {
        if (AMODE == 0) return A0[(size_t)r * K + c];
        float v = (c < 128) ? A0[(size_t)r * 128 + c] : A1[(size_t)r * 128 + (c - 128)];
        if (AMODE == 1) { if (c >= 128) v = v * p0[c - 128] + p1[c - 128]; }
        else            { v = (v - mj[si]) * rj[si] * p2[c] + p3[c]; }
        return v;
    };

    loadB(0);
    __syncthreads();

    float acc[2][8][4] = {};
    constexpr int NS = K / 32;

    #pragma unroll
    for (int s = 0; s < NS; s++) {
        if (K > 128 && s == 4) {
            __syncthreads();
            loadB(128);
            __syncthreads();
        }
        const int kc = s * 32;
        // gather this warp's 8 A fragments for the slice (registers only)
        float4 cur[2][4];
        #pragma unroll
        for (int mt2 = 0; mt2 < 2; mt2++) {
            int r = rbase + mt2 * 16;
            #pragma unroll
            for (int k8 = 0; k8 < 4; k8++) {
                int c = kc + k8 * 8 + lc;
                cur[mt2][k8] = make_float4(
                    tf32r(fetch1(r,     mt2 * 2,     c)),
                    tf32r(fetch1(r + 8, mt2 * 2 + 1, c)),
                    tf32r(fetch1(r,     mt2 * 2,     c + 4)),
                    tf32r(fetch1(r + 8, mt2 * 2 + 1, c + 4)));
            }
        }
        const int kb = (s & 3) * 4;
        #pragma unroll
        for (int k8 = 0; k8 < 4; k8++) {
            #pragma unroll
            for (int u = 0; u < 8; u++) {
                float2 b = Bs[((kb + k8) * 16 + wn * 8 + u) * 32 + lane];
                mma_tf32(acc[0][u], cur[0][k8], b);
                mma_tf32(acc[1][u], cur[1][k8], b);
            }
        }
    }

    const int ec = lc * 2;
    #pragma unroll
    for (int t = 0; t < 2; t++) {
        int m0 = row0 + wm * 32 + t * 16 + lr;
        #pragma unroll
        for (int u = 0; u < 8; u++) {
            int n = wn * 64 + u * 8 + ec;
            float b0 = bias[n], b1 = bias[n + 1];
            float v0 = acc[t][u][0] + b0;
            float v1 = acc[t][u][1] + b1;
            float v2 = acc[t][u][2] + b0;
            float v3 = acc[t][u][3] + b1;
            if (EPI == EPI_GELU) {
                v0 = 0.5f * v0 * (1.0f + erff(v0 * 0.70710678f));
                v1 = 0.5f * v1 * (1.0f + erff(v1 * 0.70710678f));
                v2 = 0.5f * v2 * (1.0f + erff(v2 * 0.70710678f));
                v3 = 0.5f * v3 * (1.0f + erff(v3 * 0.70710678f));
            } else if (EPI == EPI_RES) {
                float2 r0 = *(const float2*)(res + (size_t)m0 * 128 + n);
                float2 rr = *(const float2*)(res + (size_t)(m0 + 8) * 128 + n);
                v0 += r0.x; v1 += r0.y; v2 += rr.x; v3 += rr.y;
            }
            *(float2*)(Cm + (size_t)m0 * 128 + n)       = make_float2(v0, v1);
            *(float2*)(Cm + (size_t)(m0 + 8) * 128 + n) = make_float2(v2, v3);
        }
    }
}

// ---------------------------------------------------------------------------
// LayerNorm stats only: per-token mean & rstd over the 256-wide concat
// ---------------------------------------------------------------------------
__global__ void ln_stats_k(const float* __restrict__ x1a, const float* __restrict__ x2a,
                           float* __restrict__ mean, float* __restrict__ rstd) {
    int warp = (blockIdx.x * blockDim.x + threadIdx.x) >> 5;
    int lane = threadIdx.x & 31;
    if (warp >= Mm) return;
    float s = 0.f, sq = 0.f;
    #pragma unroll
    for (int kq = 0; kq < 4; kq++) {
        float a = x1a[(size_t)warp * 128 + lane + 32 * kq];
        float b = x2a[(size_t)warp * 128 + lane + 32 * kq];
        s += a + b; sq += a * a + b * b;
    }
    #pragma unroll
    for (int o = 16; o > 0; o >>= 1) {
        s  += __shfl_xor_sync(0xffffffffu, s, o);
        sq += __shfl_xor_sync(0xffffffffu, sq, o);
    }
    if (lane == 0) {
        float mu = s * (1.f / 256.f);
        float var = sq * (1.f / 256.f) - mu * mu;
        mean[warp] = mu;
        rstd[warp] = rsqrtf(var + 1e-5f);
    }
}

// ---------------------------------------------------------------------------
// Window attention on tensor cores (validated in R5)
// ---------------------------------------------------------------------------
constexpr int QS_STRIDE = 132;
constexpr int VS_STRIDE = 136;
constexpr int PS_STRIDE = 68;
constexpr int ATTN_SMEM = (2 * 64 * QS_STRIDE + 64 * VS_STRIDE + 64 * PS_STRIDE) * 4;

__launch_bounds__(256)
__global__ void attn_k(const float* __restrict__ q, const float* __restrict__ k,
                       const float* __restrict__ v, float* __restrict__ out) {
    extern __shared__ float sm[];
    float* Qs = sm;
    float* Ks = Qs + 64 * QS_STRIDE;
    float* Vs = Ks + 64 * QS_STRIDE;
    float* Ps = Vs + 64 * VS_STRIDE;

    const int widx = blockIdx.x;
    const int b = widx >> 6, wh = (widx >> 3) & 7, ww = widx & 7;
    const int tid  = threadIdx.x;
    const int lane = tid & 31, w = tid >> 5;
    const int wm = w & 3, wn = w >> 2;
    const int lr = lane >> 2, lc = lane & 3;

    auto grow = [&](int i) -> size_t {
        return ((size_t)(b * Nn + (wh * 7 + i / 7) * 56 + ww * 7 + (i % 7))) * 128;
    };

    for (int e = tid; e < 49 * 32; e += 256) {
        int i = e >> 5, c4 = (e & 31) * 4;
        size_t g = grow(i) + c4;
        float4 a  = *(const float4*)(q + g);
        float4 kk = *(const float4*)(k + g);
        float4 vv = *(const float4*)(v + g);
        *(float4*)(Qs + i * QS_STRIDE + c4) =
            make_float4(tf32r(a.x), tf32r(a.y), tf32r(a.z), tf32r(a.w));
        *(float4*)(Ks + i * QS_STRIDE + c4) =
            make_float4(tf32r(kk.x), tf32r(kk.y), tf32r(kk.z), tf32r(kk.w));
        *(float4*)(Vs + i * VS_STRIDE + c4) =
            make_float4(tf32r(vv.x), tf32r(vv.y), tf32r(vv.z), tf32r(vv.w));
    }
    for (int e = tid; e < 15 * QS_STRIDE; e += 256) {
        Qs[49 * QS_STRIDE + e] = 0.f;
        Ks[49 * QS_STRIDE + e] = 0.f;
    }
    for (int e = tid; e < 15 * VS_STRIDE; e += 256) Vs[49 * VS_STRIDE + e] = 0.f;
    __syncthreads();

    float acc[4][4] = {};
    #pragma unroll
    for (int k8 = 0; k8 < 16; k8++) {
        int r = wm * 16 + lr, c = k8 * 8 + lc;
        float4 a = make_float4(Qs[r * QS_STRIDE + c],     Qs[(r + 8) * QS_STRIDE + c],
                               Qs[r * QS_STRIDE + c + 4], Qs[(r + 8) * QS_STRIDE + c + 4]);
        #pragma unroll
        for (int u = 0; u < 4; u++) {
            int n = wn * 32 + u * 8 + lr;
            float2 bf = make_float2(Ks[n * QS_STRIDE + c], Ks[n * QS_STRIDE + c + 4]);
            mma_tf32(acc[u], a, bf);
        }
    }
    #pragma unroll
    for (int u = 0; u < 4; u++) {
        int r = wm * 16 + lr, n = wn * 32 + u * 8 + lc * 2;
        *(float2*)(Ps + r * PS_STRIDE + n)       = make_float2(acc[u][0], acc[u][1]);
        *(float2*)(Ps + (r + 8) * PS_STRIDE + n) = make_float2(acc[u][2], acc[u][3]);
    }
    __syncthreads();

    if (tid < 49) {
        const float scale = 0.08838834764831845f;
        float* r = Ps + tid * PS_STRIDE;
        float mx = r[0];
        #pragma unroll 7
        for (int j = 1; j < 49; j++) mx = fmaxf(mx, r[j]);
        float s = 0.f;
        #pragma unroll 7
        for (int j = 0; j < 49; j++) { float e = expf((r[j] - mx) * scale); r[j] = e; s += e; }
        float inv = 1.f / s;
        #pragma unroll 7
        for (int j = 0; j < 49; j++) r[j] = tf32r(r[j] * inv);
        #pragma unroll
        for (int j = 49; j < 64; j++) r[j] = 0.f;
    }
    __syncthreads();

    float o[8][4] = {};
    #pragma unroll
    for (int k8 = 0; k8 < 8; k8++) {
        int r = wm * 16 + lr, c = k8 * 8 + lc;
        float4 a = make_float4(Ps[r * PS_STRIDE + c],     Ps[(r + 8) * PS_STRIDE + c],
                               Ps[r * PS_STRIDE + c + 4], Ps[(r + 8) * PS_STRIDE + c + 4]);
        #pragma unroll
        for (int u = 0; u < 8; u++) {
            int n = wn * 64 + u * 8 + lr;
            float2 bf = make_float2(Vs[c * VS_STRIDE + n], Vs[(c + 4) * VS_STRIDE + n]);
            mma_tf32(o[u], a, bf);
        }
    }
    int r0 = wm * 16 + lr;
    #pragma unroll
    for (int u = 0; u < 8; u++) {
        int n = wn * 64 + u * 8 + lc * 2;
        if (r0 < 49)     *(float2*)(out + grow(r0) + n)     = make_float2(o[u][0], o[u][1]);
        if (r0 + 8 < 49) *(float2*)(out + grow(r0 + 8) + n) = make_float2(o[u][2], o[u][3]);
    }
}

// ---------------------------------------------------------------------------
// BatchNorm pieces
// ---------------------------------------------------------------------------
__global__ void bn_stats_k(const float* __restrict__ x, float* __restrict__ part) {
    int c = threadIdx.x & 127;
    int half = threadIdx.x >> 7;
    float s = 0.f, sq = 0.f;
    int rbeg = blockIdx.x * 128 + half;
    int rend = blockIdx.x * 128 + 128;
    for (int r = rbeg; r < rend; r += 2) {
        float vv = x[(size_t)r * 128 + c];
        s += vv; sq += vv * vv;
    }
    __shared__ float sh[512];
    sh[threadIdx.x] = s;
    sh[256 + threadIdx.x] = sq;
    __syncthreads();
    if (half == 0) {
        part[blockIdx.x * 256 + c]       = sh[c] + sh[128 + c];
        part[blockIdx.x * 256 + 128 + c] = sh[256 + c] + sh[256 + 128 + c];
    }
}

__global__ void bn_apply_relu_stats_k(float* __restrict__ x,
                                      const float* __restrict__ scale,
                                      const float* __restrict__ shift,
                                      float* __restrict__ part) {
    int c = threadIdx.x & 127;
    int half = threadIdx.x >> 7;
    float sc = scale[c], sh_ = shift[c];
    float s = 0.f, sq = 0.f;
    int rbeg = blockIdx.x * 128 + half;
    int rend = blockIdx.x * 128 + 128;
    for (int r = rbeg; r < rend; r += 2) {
        float vv = fmaxf(x[(size_t)r * 128 + c] * sc + sh_, 0.f);
        x[(size_t)r * 128 + c] = vv;
        s += vv; sq += vv * vv;
    }
    __shared__ float shm[512];
    shm[threadIdx.x] = s;
    shm[256 + threadIdx.x] = sq;
    __syncthreads();
    if (half == 0) {
        part[blockIdx.x * 256 + c]       = shm[c] + shm[128 + c];
        part[blockIdx.x * 256 + 128 + c] = shm[256 + c] + shm[256 + 128 + c];
    }
}

__global__ void bn_reduce_k(const float* __restrict__ part, const float* __restrict__ g,
                            const float* __restrict__ beta, float* __restrict__ scale,
                            float* __restrict__ shift) {
    int c = threadIdx.x;
    float s = 0.f, sq = 0.f;
    for (int i = 0; i < 784; i++) {
        s  += part[i * 256 + c];
        sq += part[i * 256 + 128 + c];
    }
    float mean = s / (float)Mm;
    float var  = sq / (float)Mm - mean * mean;
    float sc_  = g[c] * rsqrtf(var + 1e-5f);
    scale[c] = sc_;
    shift[c] = beta[c] - mean * sc_;
}

// ---------------------------------------------------------------------------
// Host launch
// ---------------------------------------------------------------------------
static float* symaddr(const void* devsym) {
    void* p = nullptr;
    cudaGetSymbolAddress(&p, devsym);
    return (float*)p;
}

extern "C" void kernel_launch(void* const* d_in, const int* in_sizes, int n_in,
                              void* d_out, int out_size) {
    const float* x     = (const float*)d_in[0];
    const float* fc1_w = (const float*)d_in[1];
    const float* fc1_b = (const float*)d_in[2];
    const float* fc2_w = (const float*)d_in[3];
    const float* fc2_b = (const float*)d_in[4];
    const float* fc3_w = (const float*)d_in[5];
    const float* fc3_b = (const float*)d_in[6];
    const float* fc4_w = (const float*)d_in[7];
    const float* fc4_b = (const float*)d_in[8];
    const float* fc5_w = (const float*)d_in[9];
    const float* fc5_b = (const float*)d_in[10];
    const float* fc6_w = (const float*)d_in[11];
    const float* fc6_b = (const float*)d_in[12];
    const float* ln_w  = (const float*)d_in[13];
    const float* ln_b  = (const float*)d_in[14];
    const float* q_w   = (const float*)d_in[15];
    const float* q_b   = (const float*)d_in[16];
    const float* k_w   = (const float*)d_in[17];
    const float* k_b   = (const float*)d_in[18];
    const float* v_w   = (const float*)d_in[19];
    const float* v_b   = (const float*)d_in[20];
    const float* bn1_g = (const float*)d_in[21];
    const float* bn1_b = (const float*)d_in[22];
    const float* bn2_g = (const float*)d_in[23];
    const float* bn2_b = (const float*)d_in[24];

    float* t0   = symaddr(g_t0);
    float* t1   = symaddr(g_t1);
    float* x1a  = symaddr(g_x1a);
    float* x2a  = symaddr(g_x2a);
    float* qb   = symaddr(g_q);
    float* kb   = symaddr(g_k);
    float* vb   = symaddr(g_v);
    float* att  = symaddr(g_att);
    float* stat = symaddr(g_stats);
    float* mean = stat;
    float* rstd = stat + Mm;
    float* part = symaddr(g_part);
    float* scl  = symaddr(g_scale);
    float* shf  = symaddr(g_shift);

    const int gridR = Bb * 56;
    const int gridG = Mm / 128;          // 784

    auto setsm = [](const void* f) {
        cudaFuncSetAttribute(f, cudaFuncAttributeMaxDynamicSharedMemorySize, SM_ALL);
    };
    setsm((const void*)gemm_k<128, EPI_GELU, 0, false, false>);
    setsm((const void*)gemm_k<128, EPI_RES,  0, false, false>);
    setsm((const void*)gemm_k<128, EPI_BIAS, 0, true,  true >);
    setsm((const void*)gemm_k<256, EPI_RES,  2, false, false>);
    setsm((const void*)gemm_k<256, EPI_BIAS, 1, false, false>);
    cudaFuncSetAttribute(attn_k, cudaFuncAttributeMaxDynamicSharedMemorySize, ATTN_SMEM);

    #define GEMM_ARGS(A0,A1,B,bias,res,q0,q1,q2,q3,C) \
        A0, A1, B, nullptr, nullptr, bias, nullptr, nullptr, res, q0, q1, q2, q3, C, nullptr, nullptr

    // Branch 1
    roll_k<0><<<gridR, 256>>>(x, t0);
    gemm_k<128, EPI_GELU, 0, false, false><<<gridG, 256, SM_ALL>>>(
        GEMM_ARGS(t0, nullptr, fc1_w, fc1_b, nullptr, nullptr, nullptr, nullptr, nullptr, t1));
    roll_k<1><<<gridR, 256>>>(t1, t0);
    gemm_k<128, EPI_RES, 0, false, false><<<gridG, 256, SM_ALL>>>(
        GEMM_ARGS(t0, nullptr, fc2_w, fc2_b, x, nullptr, nullptr, nullptr, nullptr, x1a));

    // Branch 2
    roll_k<2><<<gridR, 256>>>(x, t0);
    gemm_k<128, EPI_GELU, 0, false, false><<<gridG, 256, SM_ALL>>>(
        GEMM_ARGS(t0, nullptr, fc3_w, fc3_b, nullptr, nullptr, nullptr, nullptr, nullptr, t1));
    roll_k<0><<<gridR, 256>>>(t1, t0);
    gemm_k<128, EPI_RES, 0, false, false><<<gridG, 256, SM_ALL>>>(
        GEMM_ARGS(t0, nullptr, fc4_w, fc4_b, x, nullptr, nullptr, nullptr, nullptr, x2a));

    // LN stats + fc5 (LN folded into A-gather) + residual -> t0
    ln_stats_k<<<Mm / 8, 256>>>(x1a, x2a, mean, rstd);
    gemm_k<256, EPI_RES, 2, false, false><<<gridG, 256, SM_ALL>>>(
        x1a, x2a, fc5_w, nullptr, nullptr, fc5_b, nullptr, nullptr, x,
        mean, rstd, ln_w, ln_b, t0, nullptr, nullptr);

    // q/k/v in one launch (grid.y selects weight/bias/output)
    gemm_k<128, EPI_BIAS, 0, true, true><<<dim3(gridG, 3), 256, SM_ALL>>>(
        x, nullptr, q_w, k_w, v_w, q_b, k_b, v_b, nullptr,
        nullptr, nullptr, nullptr, nullptr, qb, kb, vb);

    // Window attention (tensor cores)
    attn_k<<<2048, 256, ATTN_SMEM>>>(qb, kb, vb, att);

    // BN1 -> (apply+ReLU, BN2 stats) -> BN2 folded into fc6 A-load
    bn_stats_k<<<784, 256>>>(att, part);
    bn_reduce_k<<<1, 128>>>(part, bn1_g, bn1_b, scl, shf);
    bn_apply_relu_stats_k<<<784, 256>>>(att, scl, shf, part);
    bn_reduce_k<<<1, 128>>>(part, bn2_g, bn2_b, scl, shf);

    // Final: out = [x1 | BN2(att)] @ fc6 + b
    gemm_k<256, EPI_BIAS, 1, false, false><<<gridG, 256, SM_ALL>>>(
        t0, att, fc6_w, nullptr, nullptr, fc6_b, nullptr, nullptr, nullptr,
        scl, shf, nullptr, nullptr, (float*)d_out, nullptr, nullptr);
}

// round 8
// speedup vs baseline: 1.1864x; 1.1864x over previous
#include <cuda_runtime.h>
#include <math.h>
#include <stdint.h>

constexpr int Bb = 32;
constexpr int Hh = 56;
constexpr int Ww = 56;
constexpr int Cc = 128;
constexpr int Nn = Hh * Ww;              // 3136
constexpr int Mm = Bb * Nn;              // 100352
constexpr size_t MC = (size_t)Mm * Cc;

__device__ float g_t0[MC];
__device__ float g_t1[MC];
__device__ float g_x1a[MC];
__device__ float g_x2a[MC];
__device__ float g_q[MC];
__device__ float g_k[MC];
__device__ float g_v[MC];
__device__ float g_att[MC];
__device__ float g_stats[2 * Mm];        // LN mean | rstd
__device__ float g_part[784 * 256];
__device__ float g_scale[Cc];
__device__ float g_shift[Cc];

__device__ __forceinline__ float tf32r(float x) {
    uint32_t u;
    asm("cvt.rna.tf32.f32 %0, %1;" : "=r"(u) : "f"(x));
    return __uint_as_float(u);
}

__device__ __forceinline__ void mma_tf32(float* c, const float4& a, const float2& b) {
    asm volatile(
        "mma.sync.aligned.m16n8k8.row.col.f32.tf32.tf32.f32 "
        "{%0,%1,%2,%3}, {%4,%5,%6,%7}, {%8,%9}, {%0,%1,%2,%3};"
        : "+f"(c[0]), "+f"(c[1]), "+f"(c[2]), "+f"(c[3])
        : "r"(__float_as_uint(a.x)), "r"(__float_as_uint(a.y)),
          "r"(__float_as_uint(a.z)), "r"(__float_as_uint(a.w)),
          "r"(__float_as_uint(b.x)), "r"(__float_as_uint(b.y)));
}

// ---------------------------------------------------------------------------
// Per-channel roll. MODE 0: H,+c  1: W,+c  2: W,-c
// ---------------------------------------------------------------------------
template <int MODE>
__launch_bounds__(256)
__global__ void roll_k(const float* __restrict__ in, float* __restrict__ out) {
    __shared__ float tile[56 * 128];
    const int tid = threadIdx.x;
    const int b = blockIdx.x / 56;
    const int f = blockIdx.x % 56;
    const size_t base   = (MODE == 0) ? ((size_t)b * Nn + f) * 128
                                      : ((size_t)(b * 56 + f) * 56) * 128;
    const int    stride = (MODE == 0) ? 56 * 128 : 128;

    #pragma unroll
    for (int e = tid; e < 56 * 32; e += 256) {
        int rowi = e >> 5, c4 = e & 31;
        ((float4*)tile)[rowi * 32 + c4] =
            *(const float4*)(in + base + (size_t)rowi * stride + c4 * 4);
    }
    __syncthreads();

    #pragma unroll
    for (int e = tid; e < 56 * 128; e += 256) {
        int pos = e >> 7, c = e & 127;
        int cm = c % 56;
        int src = (MODE == 2) ? pos + cm : pos - cm;
        if (src < 0) src += 56;
        if (src >= 56) src -= 56;
        out[base + (size_t)pos * stride + c] = tile[src * 128 + c];
    }
}

// ---------------------------------------------------------------------------
// TF32 GEMM. A path: coalesced LDG.128 -> XOR-swizzled row-major smem
// (conflict-free STS.128 and scalar LDS.32). B resident in fragment-order
// smem (64 KB chunk of 128 k-cols; K=256 swaps chunk once). Double-buffered
// A with register prefetch; 2 barriers per 32-k slice.
// AMODE: 0 plain A[M,K]; 1 split [A0|A1]+per-col affine on A1 (BN fold);
//        2 split [A0|A1]+per-row LayerNorm fold. QKV: grid.y selects B/bias/C.
// ---------------------------------------------------------------------------
enum { EPI_GELU = 0, EPI_BIAS = 1, EPI_RES = 2 };
constexpr int SM_ALL = 16 * 16 * 32 * 8 + 2 * 128 * 32 * 4;   // 64KB B + 32KB A = 96KB

template <int K, int EPI, int AMODE, bool BT, bool QKV>
__launch_bounds__(256, 2)
__global__ void gemm_k(const float* __restrict__ A0, const float* __restrict__ A1,
                       const float* __restrict__ B0, const float* __restrict__ B1,
                       const float* __restrict__ B2,
                       const float* __restrict__ bias0, const float* __restrict__ bias1,
                       const float* __restrict__ bias2,
                       const float* __restrict__ res,
                       const float* __restrict__ p0, const float* __restrict__ p1,
                       const float* __restrict__ p2, const float* __restrict__ p3,
                       float* __restrict__ C0, float* __restrict__ C1,
                       float* __restrict__ C2) {
    extern __shared__ float smem[];
    float2* Bs = (float2*)smem;                 // [16 k8][16 nt][32 lane]
    float*  As = smem + 16384;                  // 2 bufs x 128 rows x 32 (swizzled)

    const float* Bm = B0;
    const float* bias = bias0;
    float* Cm = C0;
    if (QKV) {
        int y = blockIdx.y;
        if (y == 1) { Bm = B1; bias = bias1; Cm = C1; }
        else if (y == 2) { Bm = B2; bias = bias2; Cm = C2; }
    }

    const int tid  = threadIdx.x;
    const int lane = tid & 31;
    const int wid  = tid >> 5;
    const int wm   = wid & 3;
    const int wn   = wid >> 2;
    const int row0 = blockIdx.x * 128;
    const int lr   = lane >> 2;
    const int lc   = lane & 3;

    auto loadB = [&](int ko) {
        for (int frag = wid; frag < 256; frag += 8) {
            int k8l = frag >> 4, nt = frag & 15;
            int kk = ko + k8l * 8 + lc, n = nt * 8 + lr;
            float b0v, b1v;
            if (BT) { b0v = Bm[(size_t)n * K + kk];   b1v = Bm[(size_t)n * K + kk + 4]; }
            else    { b0v = Bm[(size_t)kk * 128 + n]; b1v = Bm[(size_t)(kk + 4) * 128 + n]; }
            Bs[frag * 32 + lane] = make_float2(tf32r(b0v), tf32r(b1v));
        }
    };

    // ---- A producer: thread loads rows (tid>>3)+{0,32,64,96}, cols fixed c4=tid&7
    const int arow = tid >> 3;         // + i*32
    const int ac4  = tid & 7;
    float mrow[4], rrow[4];
    if (AMODE == 2) {
        #pragma unroll
        for (int i = 0; i < 4; i++) {
            int gr = row0 + arow + i * 32;
            mrow[i] = p0[gr];
            rrow[i] = p1[gr];
        }
    }

    auto fetch4 = [&](int i, int c) -> float4 {
        int gr = row0 + arow + i * 32;
        float4 v;
        if (AMODE == 0) {
            v = *(const float4*)(A0 + (size_t)gr * K + c);
        } else {
            v = (c < 128) ? *(const float4*)(A0 + (size_t)gr * 128 + c)
                          : *(const float4*)(A1 + (size_t)gr * 128 + (c - 128));
            if (AMODE == 1) {
                if (c >= 128) {
                    float4 s = *(const float4*)(p0 + c - 128);
                    float4 h = *(const float4*)(p1 + c - 128);
                    v.x = v.x * s.x + h.x; v.y = v.y * s.y + h.y;
                    v.z = v.z * s.z + h.z; v.w = v.w * s.w + h.w;
                }
            } else {
                float4 g = *(const float4*)(p2 + c);
                float4 bb = *(const float4*)(p3 + c);
                float mn = mrow[i], rs = rrow[i];
                v.x = (v.x - mn) * rs * g.x + bb.x;
                v.y = (v.y - mn) * rs * g.y + bb.y;
                v.z = (v.z - mn) * rs * g.z + bb.z;
                v.w = (v.w - mn) * rs * g.w + bb.w;
            }
        }
        return make_float4(tf32r(v.x), tf32r(v.y), tf32r(v.z), tf32r(v.w));
    };

    float4 pa[4];
    auto gather = [&](int kc) {
        int c = kc + ac4 * 4;
        #pragma unroll
        for (int i = 0; i < 4; i++) pa[i] = fetch4(i, c);
    };

    loadB(0);
    gather(0);

    float acc[2][8][4] = {};
    constexpr int NS = K / 32;

    #pragma unroll
    for (int s = 0; s < NS; s++) {
        if (K > 128 && s == 4) loadB(128);   // prior barrier ensured mma(s=3) done
        // STS swizzled: addr(row,c4) = row*32 + 4*(c4 ^ (row&7))
        const int bo = (s & 1) * 4096;
        #pragma unroll
        for (int i = 0; i < 4; i++) {
            int row = arow + i * 32;
            *(float4*)(As + bo + row * 32 + 4 * (ac4 ^ (row & 7))) = pa[i];
        }
        __syncthreads();
        if (s + 1 < NS) gather((s + 1) * 32);
        const int kb = (s & 3) * 4;
        const int bo2 = (s & 1) * 4096;
        #pragma unroll
        for (int k8 = 0; k8 < 4; k8++) {
            float4 av[2];
            #pragma unroll
            for (int mt2 = 0; mt2 < 2; mt2++) {
                int r = wm * 32 + mt2 * 16 + lr;
                int s0 = 4 * ((2 * k8) ^ lr) + lc;
                int s1 = 4 * ((2 * k8 + 1) ^ lr) + lc;
                const float* b1p = As + bo2 + r * 32;
                const float* b2p = As + bo2 + (r + 8) * 32;
                av[mt2] = make_float4(b1p[s0], b2p[s0], b1p[s1], b2p[s1]);
            }
            #pragma unroll
            for (int u = 0; u < 8; u++) {
                float2 b = Bs[((kb + k8) * 16 + wn * 8 + u) * 32 + lane];
                mma_tf32(acc[0][u], av[0], b);
                mma_tf32(acc[1][u], av[1], b);
            }
        }
        __syncthreads();
    }

    const int ec = lc * 2;
    #pragma unroll
    for (int t = 0; t < 2; t++) {
        int m0 = row0 + wm * 32 + t * 16 + lr;
        #pragma unroll
        for (int u = 0; u < 8; u++) {
            int n = wn * 64 + u * 8 + ec;
            float b0 = bias[n], b1 = bias[n + 1];
            float v0 = acc[t][u][0] + b0;
            float v1 = acc[t][u][1] + b1;
            float v2 = acc[t][u][2] + b0;
            float v3 = acc[t][u][3] + b1;
            if (EPI == EPI_GELU) {
                v0 = 0.5f * v0 * (1.0f + erff(v0 * 0.70710678f));
                v1 = 0.5f * v1 * (1.0f + erff(v1 * 0.70710678f));
                v2 = 0.5f * v2 * (1.0f + erff(v2 * 0.70710678f));
                v3 = 0.5f * v3 * (1.0f + erff(v3 * 0.70710678f));
            } else if (EPI == EPI_RES) {
                float2 r0 = *(const float2*)(res + (size_t)m0 * 128 + n);
                float2 rr = *(const float2*)(res + (size_t)(m0 + 8) * 128 + n);
                v0 += r0.x; v1 += r0.y; v2 += rr.x; v3 += rr.y;
            }
            *(float2*)(Cm + (size_t)m0 * 128 + n)       = make_float2(v0, v1);
            *(float2*)(Cm + (size_t)(m0 + 8) * 128 + n) = make_float2(v2, v3);
        }
    }
}

// ---------------------------------------------------------------------------
// LayerNorm stats only: per-token mean & rstd over the 256-wide concat
// ---------------------------------------------------------------------------
__global__ void ln_stats_k(const float* __restrict__ x1a, const float* __restrict__ x2a,
                           float* __restrict__ mean, float* __restrict__ rstd) {
    int warp = (blockIdx.x * blockDim.x + threadIdx.x) >> 5;
    int lane = threadIdx.x & 31;
    if (warp >= Mm) return;
    float s = 0.f, sq = 0.f;
    #pragma unroll
    for (int kq = 0; kq < 4; kq++) {
        float a = x1a[(size_t)warp * 128 + lane + 32 * kq];
        float b = x2a[(size_t)warp * 128 + lane + 32 * kq];
        s += a + b; sq += a * a + b * b;
    }
    #pragma unroll
    for (int o = 16; o > 0; o >>= 1) {
        s  += __shfl_xor_sync(0xffffffffu, s, o);
        sq += __shfl_xor_sync(0xffffffffu, sq, o);
    }
    if (lane == 0) {
        float mu = s * (1.f / 256.f);
        float var = sq * (1.f / 256.f) - mu * mu;
        mean[warp] = mu;
        rstd[warp] = rsqrtf(var + 1e-5f);
    }
}

// ---------------------------------------------------------------------------
// Window attention on tensor cores (validated in R5)
// ---------------------------------------------------------------------------
constexpr int QS_STRIDE = 132;
constexpr int VS_STRIDE = 136;
constexpr int PS_STRIDE = 68;
constexpr int ATTN_SMEM = (2 * 64 * QS_STRIDE + 64 * VS_STRIDE + 64 * PS_STRIDE) * 4;

__launch_bounds__(256)
__global__ void attn_k(const float* __restrict__ q, const float* __restrict__ k,
                       const float* __restrict__ v, float* __restrict__ out) {
    extern __shared__ float sm[];
    float* Qs = sm;
    float* Ks = Qs + 64 * QS_STRIDE;
    float* Vs = Ks + 64 * QS_STRIDE;
    float* Ps = Vs + 64 * VS_STRIDE;

    const int widx = blockIdx.x;
    const int b = widx >> 6, wh = (widx >> 3) & 7, ww = widx & 7;
    const int tid  = threadIdx.x;
    const int lane = tid & 31, w = tid >> 5;
    const int wm = w & 3, wn = w >> 2;
    const int lr = lane >> 2, lc = lane & 3;

    auto grow = [&](int i) -> size_t {
        return ((size_t)(b * Nn + (wh * 7 + i / 7) * 56 + ww * 7 + (i % 7))) * 128;
    };

    for (int e = tid; e < 49 * 32; e += 256) {
        int i = e >> 5, c4 = (e & 31) * 4;
        size_t g = grow(i) + c4;
        float4 a  = *(const float4*)(q + g);
        float4 kk = *(const float4*)(k + g);
        float4 vv = *(const float4*)(v + g);
        *(float4*)(Qs + i * QS_STRIDE + c4) =
            make_float4(tf32r(a.x), tf32r(a.y), tf32r(a.z), tf32r(a.w));
        *(float4*)(Ks + i * QS_STRIDE + c4) =
            make_float4(tf32r(kk.x), tf32r(kk.y), tf32r(kk.z), tf32r(kk.w));
        *(float4*)(Vs + i * VS_STRIDE + c4) =
            make_float4(tf32r(vv.x), tf32r(vv.y), tf32r(vv.z), tf32r(vv.w));
    }
    for (int e = tid; e < 15 * QS_STRIDE; e += 256) {
        Qs[49 * QS_STRIDE + e] = 0.f;
        Ks[49 * QS_STRIDE + e] = 0.f;
    }
    for (int e = tid; e < 15 * VS_STRIDE; e += 256) Vs[49 * VS_STRIDE + e] = 0.f;
    __syncthreads();

    float acc[4][4] = {};
    #pragma unroll
    for (int k8 = 0; k8 < 16; k8++) {
        int r = wm * 16 + lr, c = k8 * 8 + lc;
        float4 a = make_float4(Qs[r * QS_STRIDE + c],     Qs[(r + 8) * QS_STRIDE + c],
                               Qs[r * QS_STRIDE + c + 4], Qs[(r + 8) * QS_STRIDE + c + 4]);
        #pragma unroll
        for (int u = 0; u < 4; u++) {
            int n = wn * 32 + u * 8 + lr;
            float2 bf = make_float2(Ks[n * QS_STRIDE + c], Ks[n * QS_STRIDE + c + 4]);
            mma_tf32(acc[u], a, bf);
        }
    }
    #pragma unroll
    for (int u = 0; u < 4; u++) {
        int r = wm * 16 + lr, n = wn * 32 + u * 8 + lc * 2;
        *(float2*)(Ps + r * PS_STRIDE + n)       = make_float2(acc[u][0], acc[u][1]);
        *(float2*)(Ps + (r + 8) * PS_STRIDE + n) = make_float2(acc[u][2], acc[u][3]);
    }
    __syncthreads();

    if (tid < 49) {
        const float scale = 0.08838834764831845f;
        float* r = Ps + tid * PS_STRIDE;
        float mx = r[0];
        #pragma unroll 7
        for (int j = 1; j < 49; j++) mx = fmaxf(mx, r[j]);
        float s = 0.f;
        #pragma unroll 7
        for (int j = 0; j < 49; j++) { float e = expf((r[j] - mx) * scale); r[j] = e; s += e; }
        float inv = 1.f / s;
        #pragma unroll 7
        for (int j = 0; j < 49; j++) r[j] = tf32r(r[j] * inv);
        #pragma unroll
        for (int j = 49; j < 64; j++) r[j] = 0.f;
    }
    __syncthreads();

    float o[8][4] = {};
    #pragma unroll
    for (int k8 = 0; k8 < 8; k8++) {
        int r = wm * 16 + lr, c = k8 * 8 + lc;
        float4 a = make_float4(Ps[r * PS_STRIDE + c],     Ps[(r + 8) * PS_STRIDE + c],
                               Ps[r * PS_STRIDE + c + 4], Ps[(r + 8) * PS_STRIDE + c + 4]);
        #pragma unroll
        for (int u = 0; u < 8; u++) {
            int n = wn * 64 + u * 8 + lr;
            float2 bf = make_float2(Vs[c * VS_STRIDE + n], Vs[(c + 4) * VS_STRIDE + n]);
            mma_tf32(o[u], a, bf);
        }
    }
    int r0 = wm * 16 + lr;
    #pragma unroll
    for (int u = 0; u < 8; u++) {
        int n = wn * 64 + u * 8 + lc * 2;
        if (r0 < 49)     *(float2*)(out + grow(r0) + n)     = make_float2(o[u][0], o[u][1]);
        if (r0 + 8 < 49) *(float2*)(out + grow(r0 + 8) + n) = make_float2(o[u][2], o[u][3]);
    }
}

// ---------------------------------------------------------------------------
// BatchNorm pieces
// ---------------------------------------------------------------------------
__global__ void bn_stats_k(const float* __restrict__ x, float* __restrict__ part) {
    int c = threadIdx.x & 127;
    int half = threadIdx.x >> 7;
    float s = 0.f, sq = 0.f;
    int rbeg = blockIdx.x * 128 + half;
    int rend = blockIdx.x * 128 + 128;
    for (int r = rbeg; r < rend; r += 2) {
        float vv = x[(size_t)r * 128 + c];
        s += vv; sq += vv * vv;
    }
    __shared__ float sh[512];
    sh[threadIdx.x] = s;
    sh[256 + threadIdx.x] = sq;
    __syncthreads();
    if (half == 0) {
        part[blockIdx.x * 256 + c]       = sh[c] + sh[128 + c];
        part[blockIdx.x * 256 + 128 + c] = sh[256 + c] + sh[256 + 128 + c];
    }
}

__global__ void bn_apply_relu_stats_k(float* __restrict__ x,
                                      const float* __restrict__ scale,
                                      const float* __restrict__ shift,
                                      float* __restrict__ part) {
    int c = threadIdx.x & 127;
    int half = threadIdx.x >> 7;
    float sc = scale[c], sh_ = shift[c];
    float s = 0.f, sq = 0.f;
    int rbeg = blockIdx.x * 128 + half;
    int rend = blockIdx.x * 128 + 128;
    for (int r = rbeg; r < rend; r += 2) {
        float vv = fmaxf(x[(size_t)r * 128 + c] * sc + sh_, 0.f);
        x[(size_t)r * 128 + c] = vv;
        s += vv; sq += vv * vv;
    }
    __shared__ float shm[512];
    shm[threadIdx.x] = s;
    shm[256 + threadIdx.x] = sq;
    __syncthreads();
    if (half == 0) {
        part[blockIdx.x * 256 + c]       = shm[c] + shm[128 + c];
        part[blockIdx.x * 256 + 128 + c] = shm[256 + c] + shm[256 + 128 + c];
    }
}

__global__ void bn_reduce_k(const float* __restrict__ part, const float* __restrict__ g,
                            const float* __restrict__ beta, float* __restrict__ scale,
                            float* __restrict__ shift) {
    int c = threadIdx.x;
    float s = 0.f, sq = 0.f;
    for (int i = 0; i < 784; i++) {
        s  += part[i * 256 + c];
        sq += part[i * 256 + 128 + c];
    }
    float mean = s / (float)Mm;
    float var  = sq / (float)Mm - mean * mean;
    float sc_  = g[c] * rsqrtf(var + 1e-5f);
    scale[c] = sc_;
    shift[c] = beta[c] - mean * sc_;
}

// ---------------------------------------------------------------------------
// Host launch
// ---------------------------------------------------------------------------
static float* symaddr(const void* devsym) {
    void* p = nullptr;
    cudaGetSymbolAddress(&p, devsym);
    return (float*)p;
}

extern "C" void kernel_launch(void* const* d_in, const int* in_sizes, int n_in,
                              void* d_out, int out_size) {
    const float* x     = (const float*)d_in[0];
    const float* fc1_w = (const float*)d_in[1];
    const float* fc1_b = (const float*)d_in[2];
    const float* fc2_w = (const float*)d_in[3];
    const float* fc2_b = (const float*)d_in[4];
    const float* fc3_w = (const float*)d_in[5];
    const float* fc3_b = (const float*)d_in[6];
    const float* fc4_w = (const float*)d_in[7];
    const float* fc4_b = (const float*)d_in[8];
    const float* fc5_w = (const float*)d_in[9];
    const float* fc5_b = (const float*)d_in[10];
    const float* fc6_w = (const float*)d_in[11];
    const float* fc6_b = (const float*)d_in[12];
    const float* ln_w  = (const float*)d_in[13];
    const float* ln_b  = (const float*)d_in[14];
    const float* q_w   = (const float*)d_in[15];
    const float* q_b   = (const float*)d_in[16];
    const float* k_w   = (const float*)d_in[17];
    const float* k_b   = (const float*)d_in[18];
    const float* v_w   = (const float*)d_in[19];
    const float* v_b   = (const float*)d_in[20];
    const float* bn1_g = (const float*)d_in[21];
    const float* bn1_b = (const float*)d_in[22];
    const float* bn2_g = (const float*)d_in[23];
    const float* bn2_b = (const float*)d_in[24];

    float* t0   = symaddr(g_t0);
    float* t1   = symaddr(g_t1);
    float* x1a  = symaddr(g_x1a);
    float* x2a  = symaddr(g_x2a);
    float* qb   = symaddr(g_q);
    float* kb   = symaddr(g_k);
    float* vb   = symaddr(g_v);
    float* att  = symaddr(g_att);
    float* stat = symaddr(g_stats);
    float* mean = stat;
    float* rstd = stat + Mm;
    float* part = symaddr(g_part);
    float* scl  = symaddr(g_scale);
    float* shf  = symaddr(g_shift);

    const int gridR = Bb * 56;
    const int gridG = Mm / 128;          // 784

    auto setsm = [](const void* f) {
        cudaFuncSetAttribute(f, cudaFuncAttributeMaxDynamicSharedMemorySize, SM_ALL);
    };
    setsm((const void*)gemm_k<128, EPI_GELU, 0, false, false>);
    setsm((const void*)gemm_k<128, EPI_RES,  0, false, false>);
    setsm((const void*)gemm_k<128, EPI_BIAS, 0, true,  true >);
    setsm((const void*)gemm_k<256, EPI_RES,  2, false, false>);
    setsm((const void*)gemm_k<256, EPI_BIAS, 1, false, false>);
    cudaFuncSetAttribute(attn_k, cudaFuncAttributeMaxDynamicSharedMemorySize, ATTN_SMEM);

    #define GEMM_ARGS(A0,A1,B,bias,res,q0,q1,q2,q3,C) \
        A0, A1, B, nullptr, nullptr, bias, nullptr, nullptr, res, q0, q1, q2, q3, C, nullptr, nullptr

    // Branch 1
    roll_k<0><<<gridR, 256>>>(x, t0);
    gemm_k<128, EPI_GELU, 0, false, false><<<gridG, 256, SM_ALL>>>(
        GEMM_ARGS(t0, nullptr, fc1_w, fc1_b, nullptr, nullptr, nullptr, nullptr, nullptr, t1));
    roll_k<1><<<gridR, 256>>>(t1, t0);
    gemm_k<128, EPI_RES, 0, false, false><<<gridG, 256, SM_ALL>>>(
        GEMM_ARGS(t0, nullptr, fc2_w, fc2_b, x, nullptr, nullptr, nullptr, nullptr, x1a));

    // Branch 2
    roll_k<2><<<gridR, 256>>>(x, t0);
    gemm_k<128, EPI_GELU, 0, false, false><<<gridG, 256, SM_ALL>>>(
        GEMM_ARGS(t0, nullptr, fc3_w, fc3_b, nullptr, nullptr, nullptr, nullptr, nullptr, t1));
    roll_k<0><<<gridR, 256>>>(t1, t0);
    gemm_k<128, EPI_RES, 0, false, false><<<gridG, 256, SM_ALL>>>(
        GEMM_ARGS(t0, nullptr, fc4_w, fc4_b, x, nullptr, nullptr, nullptr, nullptr, x2a));

    // LN stats + fc5 (LN folded into A-gather) + residual -> t0
    ln_stats_k<<<Mm / 8, 256>>>(x1a, x2a, mean, rstd);
    gemm_k<256, EPI_RES, 2, false, false><<<gridG, 256, SM_ALL>>>(
        x1a, x2a, fc5_w, nullptr, nullptr, fc5_b, nullptr, nullptr, x,
        mean, rstd, ln_w, ln_b, t0, nullptr, nullptr);

    // q/k/v in one launch (grid.y selects weight/bias/output)
    gemm_k<128, EPI_BIAS, 0, true, true><<<dim3(gridG, 3), 256, SM_ALL>>>(
        x, nullptr, q_w, k_w, v_w, q_b, k_b, v_b, nullptr,
        nullptr, nullptr, nullptr, nullptr, qb, kb, vb);

    // Window attention (tensor cores)
    attn_k<<<2048, 256, ATTN_SMEM>>>(qb, kb, vb, att);

    // BN1 -> (apply+ReLU, BN2 stats) -> BN2 folded into fc6 A-load
    bn_stats_k<<<784, 256>>>(att, part);
    bn_reduce_k<<<1, 128>>>(part, bn1_g, bn1_b, scl, shf);
    bn_apply_relu_stats_k<<<784, 256>>>(att, scl, shf, part);
    bn_reduce_k<<<1, 128>>>(part, bn2_g, bn2_b, scl, shf);

    // Final: out = [x1 | BN2(att)] @ fc6 + b
    gemm_k<256, EPI_BIAS, 1, false, false><<<gridG, 256, SM_ALL>>>(
        t0, att, fc6_w, nullptr, nullptr, fc6_b, nullptr, nullptr, nullptr,
        scl, shf, nullptr, nullptr, (float*)d_out, nullptr, nullptr);
}

// round 9
// speedup vs baseline: 1.1915x; 1.0043x over previous
#include <cuda_runtime.h>
#include <math.h>
#include <stdint.h>

constexpr int Bb = 32;
constexpr int Hh = 56;
constexpr int Ww = 56;
constexpr int Cc = 128;
constexpr int Nn = Hh * Ww;              // 3136
constexpr int Mm = Bb * Nn;              // 100352
constexpr size_t MC = (size_t)Mm * Cc;

__device__ float g_t0[MC];
__device__ float g_t1[MC];
__device__ float g_x1a[MC];
__device__ float g_x2a[MC];
__device__ float g_q[MC];
__device__ float g_k[MC];
__device__ float g_v[MC];
__device__ float g_att[MC];
__device__ float g_stats[2 * Mm];        // LN mean | rstd
__device__ float g_part[784 * 256];
__device__ float g_scale[Cc];
__device__ float g_shift[Cc];

__device__ __forceinline__ float tf32r(float x) {
    uint32_t u;
    asm("cvt.rna.tf32.f32 %0, %1;" : "=r"(u) : "f"(x));
    return __uint_as_float(u);
}

__device__ __forceinline__ void mma_tf32(float* c, const float4& a, const float2& b) {
    asm volatile(
        "mma.sync.aligned.m16n8k8.row.col.f32.tf32.tf32.f32 "
        "{%0,%1,%2,%3}, {%4,%5,%6,%7}, {%8,%9}, {%0,%1,%2,%3};"
        : "+f"(c[0]), "+f"(c[1]), "+f"(c[2]), "+f"(c[3])
        : "r"(__float_as_uint(a.x)), "r"(__float_as_uint(a.y)),
          "r"(__float_as_uint(a.z)), "r"(__float_as_uint(a.w)),
          "r"(__float_as_uint(b.x)), "r"(__float_as_uint(b.y)));
}

// ---------------------------------------------------------------------------
// Per-channel roll. MODE 0: H,+c  1: W,+c  2: W,-c
// ---------------------------------------------------------------------------
template <int MODE>
__launch_bounds__(256)
__global__ void roll_k(const float* __restrict__ in, float* __restrict__ out) {
    __shared__ float tile[56 * 128];
    const int tid = threadIdx.x;
    const int b = blockIdx.x / 56;
    const int f = blockIdx.x % 56;
    const size_t base   = (MODE == 0) ? ((size_t)b * Nn + f) * 128
                                      : ((size_t)(b * 56 + f) * 56) * 128;
    const int    stride = (MODE == 0) ? 56 * 128 : 128;

    #pragma unroll
    for (int e = tid; e < 56 * 32; e += 256) {
        int rowi = e >> 5, c4 = e & 31;
        ((float4*)tile)[rowi * 32 + c4] =
            *(const float4*)(in + base + (size_t)rowi * stride + c4 * 4);
    }
    __syncthreads();

    #pragma unroll
    for (int e = tid; e < 56 * 128; e += 256) {
        int pos = e >> 7, c = e & 127;
        int cm = c % 56;
        int src = (MODE == 2) ? pos + cm : pos - cm;
        if (src < 0) src += 56;
        if (src >= 56) src -= 56;
        out[base + (size_t)pos * stride + c] = tile[src * 128 + c];
    }
}

// ---------------------------------------------------------------------------
// TF32 GEMM. Coalesced LDG.128 -> XOR-swizzled smem A (conflict-free both
// sides). Double register-set prefetch (distance 2), ONE barrier per slice.
// B resident fragment-order smem (64 KB chunk; K=256 swaps once, extra sync).
// AMODE: 0 plain A[M,K]; 1 split+per-col affine on A1 (BN); 2 split+LN fold.
// QKV: grid.y selects B/bias/C.
// ---------------------------------------------------------------------------
enum { EPI_GELU = 0, EPI_BIAS = 1, EPI_RES = 2 };
constexpr int SM_ALL = 16 * 16 * 32 * 8 + 2 * 128 * 32 * 4;   // 64KB B + 32KB A

template <int K, int EPI, int AMODE, bool BT, bool QKV>
__launch_bounds__(256, 2)
__global__ void gemm_k(const float* __restrict__ A0, const float* __restrict__ A1,
                       const float* __restrict__ B0, const float* __restrict__ B1,
                       const float* __restrict__ B2,
                       const float* __restrict__ bias0, const float* __restrict__ bias1,
                       const float* __restrict__ bias2,
                       const float* __restrict__ res,
                       const float* __restrict__ p0, const float* __restrict__ p1,
                       const float* __restrict__ p2, const float* __restrict__ p3,
                       float* __restrict__ C0, float* __restrict__ C1,
                       float* __restrict__ C2) {
    extern __shared__ float smem[];
    float2* Bs = (float2*)smem;                 // [16 k8][16 nt][32 lane]
    float*  As = smem + 16384;                  // 2 bufs x 128 rows x 32 (swizzled)

    const float* Bm = B0;
    const float* bias = bias0;
    float* Cm = C0;
    if (QKV) {
        int y = blockIdx.y;
        if (y == 1) { Bm = B1; bias = bias1; Cm = C1; }
        else if (y == 2) { Bm = B2; bias = bias2; Cm = C2; }
    }

    const int tid  = threadIdx.x;
    const int lane = tid & 31;
    const int wid  = tid >> 5;
    const int wm   = wid & 3;
    const int wn   = wid >> 2;
    const int row0 = blockIdx.x * 128;
    const int lr   = lane >> 2;
    const int lc   = lane & 3;

    auto loadB = [&](int ko) {
        for (int frag = wid; frag < 256; frag += 8) {
            int k8l = frag >> 4, nt = frag & 15;
            int kk = ko + k8l * 8 + lc, n = nt * 8 + lr;
            float b0v, b1v;
            if (BT) { b0v = Bm[(size_t)n * K + kk];   b1v = Bm[(size_t)n * K + kk + 4]; }
            else    { b0v = Bm[(size_t)kk * 128 + n]; b1v = Bm[(size_t)(kk + 4) * 128 + n]; }
            Bs[frag * 32 + lane] = make_float2(tf32r(b0v), tf32r(b1v));
        }
    };

    // ---- A producer: thread loads rows (tid>>3)+{0,32,64,96}, c4 block tid&7
    const int arow = tid >> 3;
    const int ac4  = tid & 7;
    float mrow[4], rrow[4];
    if (AMODE == 2) {
        #pragma unroll
        for (int i = 0; i < 4; i++) {
            int gr = row0 + arow + i * 32;
            mrow[i] = p0[gr];
            rrow[i] = p1[gr];
        }
    }

    auto fetch4 = [&](int i, int c) -> float4 {
        int gr = row0 + arow + i * 32;
        float4 v;
        if (AMODE == 0) {
            v = *(const float4*)(A0 + (size_t)gr * K + c);
        } else {
            v = (c < 128) ? *(const float4*)(A0 + (size_t)gr * 128 + c)
                          : *(const float4*)(A1 + (size_t)gr * 128 + (c - 128));
            if (AMODE == 1) {
                if (c >= 128) {
                    float4 s = *(const float4*)(p0 + c - 128);
                    float4 h = *(const float4*)(p1 + c - 128);
                    v.x = v.x * s.x + h.x; v.y = v.y * s.y + h.y;
                    v.z = v.z * s.z + h.z; v.w = v.w * s.w + h.w;
                }
            } else {
                float4 g = *(const float4*)(p2 + c);
                float4 bb = *(const float4*)(p3 + c);
                float mn = mrow[i], rs = rrow[i];
                v.x = (v.x - mn) * rs * g.x + bb.x;
                v.y = (v.y - mn) * rs * g.y + bb.y;
                v.z = (v.z - mn) * rs * g.z + bb.z;
                v.w = (v.w - mn) * rs * g.w + bb.w;
            }
        }
        return make_float4(tf32r(v.x), tf32r(v.y), tf32r(v.z), tf32r(v.w));
    };

    float4 pa[2][4];
    auto gather = [&](int kc, int set) {
        int c = kc + ac4 * 4;
        #pragma unroll
        for (int i = 0; i < 4; i++) pa[set][i] = fetch4(i, c);
    };

    loadB(0);
    gather(0, 0);
    gather(32, 1);

    float acc[2][8][4] = {};
    constexpr int NS = K / 32;

    #pragma unroll
    for (int s = 0; s < NS; s++) {
        const int set = s & 1;
        const int bo = set * 4096;
        // STS swizzled: addr(row,c4) = row*32 + 4*(c4 ^ (row&7))
        #pragma unroll
        for (int i = 0; i < 4; i++) {
            int row = arow + i * 32;
            *(float4*)(As + bo + row * 32 + 4 * (ac4 ^ (row & 7))) = pa[set][i];
        }
        __syncthreads();
        if (K > 128 && s == 4) {            // swap B chunk (all warps past mma(3))
            loadB(128);
            __syncthreads();
        }
        if (s + 2 < NS) gather((s + 2) * 32, set);
        const int kb = (s & 3) * 4;
        #pragma unroll
        for (int k8 = 0; k8 < 4; k8++) {
            float4 av[2];
            #pragma unroll
            for (int mt2 = 0; mt2 < 2; mt2++) {
                int r = wm * 32 + mt2 * 16 + lr;
                int s0 = 4 * ((2 * k8) ^ lr) + lc;
                int s1 = 4 * ((2 * k8 + 1) ^ lr) + lc;
                const float* b1p = As + bo + r * 32;
                const float* b2p = As + bo + (r + 8) * 32;
                av[mt2] = make_float4(b1p[s0], b2p[s0], b1p[s1], b2p[s1]);
            }
            #pragma unroll
            for (int u = 0; u < 8; u++) {
                float2 b = Bs[((kb + k8) * 16 + wn * 8 + u) * 32 + lane];
                mma_tf32(acc[0][u], av[0], b);
                mma_tf32(acc[1][u], av[1], b);
            }
        }
    }

    const int ec = lc * 2;
    #pragma unroll
    for (int t = 0; t < 2; t++) {
        int m0 = row0 + wm * 32 + t * 16 + lr;
        #pragma unroll
        for (int u = 0; u < 8; u++) {
            int n = wn * 64 + u * 8 + ec;
            float b0 = bias[n], b1 = bias[n + 1];
            float v0 = acc[t][u][0] + b0;
            float v1 = acc[t][u][1] + b1;
            float v2 = acc[t][u][2] + b0;
            float v3 = acc[t][u][3] + b1;
            if (EPI == EPI_GELU) {
                v0 = 0.5f * v0 * (1.0f + erff(v0 * 0.70710678f));
                v1 = 0.5f * v1 * (1.0f + erff(v1 * 0.70710678f));
                v2 = 0.5f * v2 * (1.0f + erff(v2 * 0.70710678f));
                v3 = 0.5f * v3 * (1.0f + erff(v3 * 0.70710678f));
            } else if (EPI == EPI_RES) {
                float2 r0 = *(const float2*)(res + (size_t)m0 * 128 + n);
                float2 rr = *(const float2*)(res + (size_t)(m0 + 8) * 128 + n);
                v0 += r0.x; v1 += r0.y; v2 += rr.x; v3 += rr.y;
            }
            *(float2*)(Cm + (size_t)m0 * 128 + n)       = make_float2(v0, v1);
            *(float2*)(Cm + (size_t)(m0 + 8) * 128 + n) = make_float2(v2, v3);
        }
    }
}

// ---------------------------------------------------------------------------
// LayerNorm stats only: per-token mean & rstd over the 256-wide concat
// ---------------------------------------------------------------------------
__global__ void ln_stats_k(const float* __restrict__ x1a, const float* __restrict__ x2a,
                           float* __restrict__ mean, float* __restrict__ rstd) {
    int warp = (blockIdx.x * blockDim.x + threadIdx.x) >> 5;
    int lane = threadIdx.x & 31;
    if (warp >= Mm) return;
    float s = 0.f, sq = 0.f;
    #pragma unroll
    for (int kq = 0; kq < 4; kq++) {
        float a = x1a[(size_t)warp * 128 + lane + 32 * kq];
        float b = x2a[(size_t)warp * 128 + lane + 32 * kq];
        s += a + b; sq += a * a + b * b;
    }
    #pragma unroll
    for (int o = 16; o > 0; o >>= 1) {
        s  += __shfl_xor_sync(0xffffffffu, s, o);
        sq += __shfl_xor_sync(0xffffffffu, sq, o);
    }
    if (lane == 0) {
        float mu = s * (1.f / 256.f);
        float var = sq * (1.f / 256.f) - mu * mu;
        mean[warp] = mu;
        rstd[warp] = rsqrtf(var + 1e-5f);
    }
}

// ---------------------------------------------------------------------------
// Window attention on tensor cores (validated in R5)
// ---------------------------------------------------------------------------
constexpr int QS_STRIDE = 132;
constexpr int VS_STRIDE = 136;
constexpr int PS_STRIDE = 68;
constexpr int ATTN_SMEM = (2 * 64 * QS_STRIDE + 64 * VS_STRIDE + 64 * PS_STRIDE) * 4;

__launch_bounds__(256)
__global__ void attn_k(const float* __restrict__ q, const float* __restrict__ k,
                       const float* __restrict__ v, float* __restrict__ out) {
    extern __shared__ float sm[];
    float* Qs = sm;
    float* Ks = Qs + 64 * QS_STRIDE;
    float* Vs = Ks + 64 * QS_STRIDE;
    float* Ps = Vs + 64 * VS_STRIDE;

    const int widx = blockIdx.x;
    const int b = widx >> 6, wh = (widx >> 3) & 7, ww = widx & 7;
    const int tid  = threadIdx.x;
    const int lane = tid & 31, w = tid >> 5;
    const int wm = w & 3, wn = w >> 2;
    const int lr = lane >> 2, lc = lane & 3;

    auto grow = [&](int i) -> size_t {
        return ((size_t)(b * Nn + (wh * 7 + i / 7) * 56 + ww * 7 + (i % 7))) * 128;
    };

    for (int e = tid; e < 49 * 32; e += 256) {
        int i = e >> 5, c4 = (e & 31) * 4;
        size_t g = grow(i) + c4;
        float4 a  = *(const float4*)(q + g);
        float4 kk = *(const float4*)(k + g);
        float4 vv = *(const float4*)(v + g);
        *(float4*)(Qs + i * QS_STRIDE + c4) =
            make_float4(tf32r(a.x), tf32r(a.y), tf32r(a.z), tf32r(a.w));
        *(float4*)(Ks + i * QS_STRIDE + c4) =
            make_float4(tf32r(kk.x), tf32r(kk.y), tf32r(kk.z), tf32r(kk.w));
        *(float4*)(Vs + i * VS_STRIDE + c4) =
            make_float4(tf32r(vv.x), tf32r(vv.y), tf32r(vv.z), tf32r(vv.w));
    }
    for (int e = tid; e < 15 * QS_STRIDE; e += 256) {
        Qs[49 * QS_STRIDE + e] = 0.f;
        Ks[49 * QS_STRIDE + e] = 0.f;
    }
    for (int e = tid; e < 15 * VS_STRIDE; e += 256) Vs[49 * VS_STRIDE + e] = 0.f;
    __syncthreads();

    float acc[4][4] = {};
    #pragma unroll
    for (int k8 = 0; k8 < 16; k8++) {
        int r = wm * 16 + lr, c = k8 * 8 + lc;
        float4 a = make_float4(Qs[r * QS_STRIDE + c],     Qs[(r + 8) * QS_STRIDE + c],
                               Qs[r * QS_STRIDE + c + 4], Qs[(r + 8) * QS_STRIDE + c + 4]);
        #pragma unroll
        for (int u = 0; u < 4; u++) {
            int n = wn * 32 + u * 8 + lr;
            float2 bf = make_float2(Ks[n * QS_STRIDE + c], Ks[n * QS_STRIDE + c + 4]);
            mma_tf32(acc[u], a, bf);
        }
    }
    #pragma unroll
    for (int u = 0; u < 4; u++) {
        int r = wm * 16 + lr, n = wn * 32 + u * 8 + lc * 2;
        *(float2*)(Ps + r * PS_STRIDE + n)       = make_float2(acc[u][0], acc[u][1]);
        *(float2*)(Ps + (r + 8) * PS_STRIDE + n) = make_float2(acc[u][2], acc[u][3]);
    }
    __syncthreads();

    if (tid < 49) {
        const float scale = 0.08838834764831845f;
        float* r = Ps + tid * PS_STRIDE;
        float mx = r[0];
        #pragma unroll 7
        for (int j = 1; j < 49; j++) mx = fmaxf(mx, r[j]);
        float s = 0.f;
        #pragma unroll 7
        for (int j = 0; j < 49; j++) { float e = expf((r[j] - mx) * scale); r[j] = e; s += e; }
        float inv = 1.f / s;
        #pragma unroll 7
        for (int j = 0; j < 49; j++) r[j] = tf32r(r[j] * inv);
        #pragma unroll
        for (int j = 49; j < 64; j++) r[j] = 0.f;
    }
    __syncthreads();

    float o[8][4] = {};
    #pragma unroll
    for (int k8 = 0; k8 < 8; k8++) {
        int r = wm * 16 + lr, c = k8 * 8 + lc;
        float4 a = make_float4(Ps[r * PS_STRIDE + c],     Ps[(r + 8) * PS_STRIDE + c],
                               Ps[r * PS_STRIDE + c + 4], Ps[(r + 8) * PS_STRIDE + c + 4]);
        #pragma unroll
        for (int u = 0; u < 8; u++) {
            int n = wn * 64 + u * 8 + lr;
            float2 bf = make_float2(Vs[c * VS_STRIDE + n], Vs[(c + 4) * VS_STRIDE + n]);
            mma_tf32(o[u], a, bf);
        }
    }
    int r0 = wm * 16 + lr;
    #pragma unroll
    for (int u = 0; u < 8; u++) {
        int n = wn * 64 + u * 8 + lc * 2;
        if (r0 < 49)     *(float2*)(out + grow(r0) + n)     = make_float2(o[u][0], o[u][1]);
        if (r0 + 8 < 49) *(float2*)(out + grow(r0 + 8) + n) = make_float2(o[u][2], o[u][3]);
    }
}

// ---------------------------------------------------------------------------
// BatchNorm pieces
// ---------------------------------------------------------------------------
__global__ void bn_stats_k(const float* __restrict__ x, float* __restrict__ part) {
    int c = threadIdx.x & 127;
    int half = threadIdx.x >> 7;
    float s = 0.f, sq = 0.f;
    int rbeg = blockIdx.x * 128 + half;
    int rend = blockIdx.x * 128 + 128;
    for (int r = rbeg; r < rend; r += 2) {
        float vv = x[(size_t)r * 128 + c];
        s += vv; sq += vv * vv;
    }
    __shared__ float sh[512];
    sh[threadIdx.x] = s;
    sh[256 + threadIdx.x] = sq;
    __syncthreads();
    if (half == 0) {
        part[blockIdx.x * 256 + c]       = sh[c] + sh[128 + c];
        part[blockIdx.x * 256 + 128 + c] = sh[256 + c] + sh[256 + 128 + c];
    }
}

__global__ void bn_apply_relu_stats_k(float* __restrict__ x,
                                      const float* __restrict__ scale,
                                      const float* __restrict__ shift,
                                      float* __restrict__ part) {
    int c = threadIdx.x & 127;
    int half = threadIdx.x >> 7;
    float sc = scale[c], sh_ = shift[c];
    float s = 0.f, sq = 0.f;
    int rbeg = blockIdx.x * 128 + half;
    int rend = blockIdx.x * 128 + 128;
    for (int r = rbeg; r < rend; r += 2) {
        float vv = fmaxf(x[(size_t)r * 128 + c] * sc + sh_, 0.f);
        x[(size_t)r * 128 + c] = vv;
        s += vv; sq += vv * vv;
    }
    __shared__ float shm[512];
    shm[threadIdx.x] = s;
    shm[256 + threadIdx.x] = sq;
    __syncthreads();
    if (half == 0) {
        part[blockIdx.x * 256 + c]       = shm[c] + shm[128 + c];
        part[blockIdx.x * 256 + 128 + c] = shm[256 + c] + shm[256 + 128 + c];
    }
}

__global__ void bn_reduce_k(const float* __restrict__ part, const float* __restrict__ g,
                            const float* __restrict__ beta, float* __restrict__ scale,
                            float* __restrict__ shift) {
    int c = threadIdx.x;
    float s = 0.f, sq = 0.f;
    for (int i = 0; i < 784; i++) {
        s  += part[i * 256 + c];
        sq += part[i * 256 + 128 + c];
    }
    float mean = s / (float)Mm;
    float var  = sq / (float)Mm - mean * mean;
    float sc_  = g[c] * rsqrtf(var + 1e-5f);
    scale[c] = sc_;
    shift[c] = beta[c] - mean * sc_;
}

// ---------------------------------------------------------------------------
// Host launch
// ---------------------------------------------------------------------------
static float* symaddr(const void* devsym) {
    void* p = nullptr;
    cudaGetSymbolAddress(&p, devsym);
    return (float*)p;
}

extern "C" void kernel_launch(void* const* d_in, const int* in_sizes, int n_in,
                              void* d_out, int out_size) {
    const float* x     = (const float*)d_in[0];
    const float* fc1_w = (const float*)d_in[1];
    const float* fc1_b = (const float*)d_in[2];
    const float* fc2_w = (const float*)d_in[3];
    const float* fc2_b = (const float*)d_in[4];
    const float* fc3_w = (const float*)d_in[5];
    const float* fc3_b = (const float*)d_in[6];
    const float* fc4_w = (const float*)d_in[7];
    const float* fc4_b = (const float*)d_in[8];
    const float* fc5_w = (const float*)d_in[9];
    const float* fc5_b = (const float*)d_in[10];
    const float* fc6_w = (const float*)d_in[11];
    const float* fc6_b = (const float*)d_in[12];
    const float* ln_w  = (const float*)d_in[13];
    const float* ln_b  = (const float*)d_in[14];
    const float* q_w   = (const float*)d_in[15];
    const float* q_b   = (const float*)d_in[16];
    const float* k_w   = (const float*)d_in[17];
    const float* k_b   = (const float*)d_in[18];
    const float* v_w   = (const float*)d_in[19];
    const float* v_b   = (const float*)d_in[20];
    const float* bn1_g = (const float*)d_in[21];
    const float* bn1_b = (const float*)d_in[22];
    const float* bn2_g = (const float*)d_in[23];
    const float* bn2_b = (const float*)d_in[24];

    float* t0   = symaddr(g_t0);
    float* t1   = symaddr(g_t1);
    float* x1a  = symaddr(g_x1a);
    float* x2a  = symaddr(g_x2a);
    float* qb   = symaddr(g_q);
    float* kb   = symaddr(g_k);
    float* vb   = symaddr(g_v);
    float* att  = symaddr(g_att);
    float* stat = symaddr(g_stats);
    float* mean = stat;
    float* rstd = stat + Mm;
    float* part = symaddr(g_part);
    float* scl  = symaddr(g_scale);
    float* shf  = symaddr(g_shift);

    const int gridR = Bb * 56;
    const int gridG = Mm / 128;          // 784

    auto setsm = [](const void* f) {
        cudaFuncSetAttribute(f, cudaFuncAttributeMaxDynamicSharedMemorySize, SM_ALL);
    };
    setsm((const void*)gemm_k<128, EPI_GELU, 0, false, false>);
    setsm((const void*)gemm_k<128, EPI_RES,  0, false, false>);
    setsm((const void*)gemm_k<128, EPI_BIAS, 0, true,  true >);
    setsm((const void*)gemm_k<256, EPI_RES,  2, false, false>);
    setsm((const void*)gemm_k<256, EPI_BIAS, 1, false, false>);
    cudaFuncSetAttribute(attn_k, cudaFuncAttributeMaxDynamicSharedMemorySize, ATTN_SMEM);

    #define GEMM_ARGS(A0,A1,B,bias,res,q0,q1,q2,q3,C) \
        A0, A1, B, nullptr, nullptr, bias, nullptr, nullptr, res, q0, q1, q2, q3, C, nullptr, nullptr

    // Branch 1
    roll_k<0><<<gridR, 256>>>(x, t0);
    gemm_k<128, EPI_GELU, 0, false, false><<<gridG, 256, SM_ALL>>>(
        GEMM_ARGS(t0, nullptr, fc1_w, fc1_b, nullptr, nullptr, nullptr, nullptr, nullptr, t1));
    roll_k<1><<<gridR, 256>>>(t1, t0);
    gemm_k<128, EPI_RES, 0, false, false><<<gridG, 256, SM_ALL>>>(
        GEMM_ARGS(t0, nullptr, fc2_w, fc2_b, x, nullptr, nullptr, nullptr, nullptr, x1a));

    // Branch 2
    roll_k<2><<<gridR, 256>>>(x, t0);
    gemm_k<128, EPI_GELU, 0, false, false><<<gridG, 256, SM_ALL>>>(
        GEMM_ARGS(t0, nullptr, fc3_w, fc3_b, nullptr, nullptr, nullptr, nullptr, nullptr, t1));
    roll_k<0><<<gridR, 256>>>(t1, t0);
    gemm_k<128, EPI_RES, 0, false, false><<<gridG, 256, SM_ALL>>>(
        GEMM_ARGS(t0, nullptr, fc4_w, fc4_b, x, nullptr, nullptr, nullptr, nullptr, x2a));

    // LN stats + fc5 (LN folded into A-gather) + residual -> t0
    ln_stats_k<<<Mm / 8, 256>>>(x1a, x2a, mean, rstd);
    gemm_k<256, EPI_RES, 2, false, false><<<gridG, 256, SM_ALL>>>(
        x1a, x2a, fc5_w, nullptr, nullptr, fc5_b, nullptr, nullptr, x,
        mean, rstd, ln_w, ln_b, t0, nullptr, nullptr);

    // q/k/v in one launch (grid.y selects weight/bias/output)
    gemm_k<128, EPI_BIAS, 0, true, true><<<dim3(gridG, 3), 256, SM_ALL>>>(
        x, nullptr, q_w, k_w, v_w, q_b, k_b, v_b, nullptr,
        nullptr, nullptr, nullptr, nullptr, qb, kb, vb);

    // Window attention (tensor cores)
    attn_k<<<2048, 256, ATTN_SMEM>>>(qb, kb, vb, att);

    // BN1 -> (apply+ReLU, BN2 stats) -> BN2 folded into fc6 A-load
    bn_stats_k<<<784, 256>>>(att, part);
    bn_reduce_k<<<1, 128>>>(part, bn1_g, bn1_b, scl, shf);
    bn_apply_relu_stats_k<<<784, 256>>>(att, scl, shf, part);
    bn_reduce_k<<<1, 128>>>(part, bn2_g, bn2_b, scl, shf);

    // Final: out = [x1 | BN2(att)] @ fc6 + b
    gemm_k<256, EPI_BIAS, 1, false, false><<<gridG, 256, SM_ALL>>>(
        t0, att, fc6_w, nullptr, nullptr, fc6_b, nullptr, nullptr, nullptr,
        scl, shf, nullptr, nullptr, (float*)d_out, nullptr, nullptr);
}